// round 12
// baseline (speedup 1.0000x reference)
#include <cuda_runtime.h>
#include <cuda_bf16.h>

#define BATCH 16
#define NN    1024
#define DD    64
#define EPSF      0.1f
#define INV_EPS   10.0f
#define LOG_MU   (-6.9314616f)   // log(1/1024 + 1e-8)
#define THRESH    0.1f
#define MAX_ITER  100
#define GB        128            // flat persistent grid: 128 blocks <= 148 SMs (co-resident)
#define TB        1024
#define XS        68             // smem strides: (row*68+col)%32 == (row*4+col)%32

// ---------------- device scratch (static; NO launch-time zero-init needed) ----------------
__device__ __nv_bfloat16 g_Kh[BATCH * NN * NN];  // 32 MB bf16 K
__device__ float g_ys[BATCH * NN * DD];          // softmaxed y (fp32)
__device__ float g_y2[BATCH * NN];
__device__ float g_u [BATCH * NN];
__device__ float g_v [BATCH * NN];
__device__ float g_a [BATCH * NN];
__device__ float g_b [BATCH * NN];
__device__ float g_errBlk[GB];                   // per-block err partials (plain stores)
__device__ float g_costP [GB];                   // per-block cost partials (plain stores)
__device__ unsigned g_bar_cnt;                   // free-running barrier (never reset)
__device__ unsigned g_bar_gen;

// ---------------- free-running software grid barrier (all GB blocks co-resident) ----------------
__device__ __forceinline__ void grid_barrier() {
    __threadfence();
    __syncthreads();
    if (threadIdx.x == 0) {
        unsigned gen = *((volatile unsigned*)&g_bar_gen);
        if (atomicAdd(&g_bar_cnt, 1u) == GB - 1u) {
            g_bar_cnt = 0u;
            __threadfence();
            *((volatile unsigned*)&g_bar_gen) = gen + 1u;
        } else {
            while (*((volatile unsigned*)&g_bar_gen) == gen) { __nanosleep(64); }
        }
    }
    __syncthreads();
}

__device__ __forceinline__ float to_tf32(float x) {
    asm("cvt.rna.tf32.f32 %0, %0;" : "+f"(x));
    return x;
}

__device__ __forceinline__ float dot8(uint4 q, float4 b0, float4 b1) {
    float2 p0 = __bfloat1622float2(*(const __nv_bfloat162*)&q.x);
    float2 p1 = __bfloat1622float2(*(const __nv_bfloat162*)&q.y);
    float2 p2 = __bfloat1622float2(*(const __nv_bfloat162*)&q.z);
    float2 p3 = __bfloat1622float2(*(const __nv_bfloat162*)&q.w);
    return p0.x*b0.x + p0.y*b0.y + p1.x*b0.z + p1.y*b0.w
         + p2.x*b1.x + p2.y*b1.y + p3.x*b1.z + p3.y*b1.w;
}

__device__ __forceinline__ float dot8log(uint4 q, float4 b0, float4 b1) {
    float2 p0 = __bfloat1622float2(*(const __nv_bfloat162*)&q.x);
    float2 p1 = __bfloat1622float2(*(const __nv_bfloat162*)&q.y);
    float2 p2 = __bfloat1622float2(*(const __nv_bfloat162*)&q.z);
    float2 p3 = __bfloat1622float2(*(const __nv_bfloat162*)&q.w);
    return p0.x*b0.x*__logf(p0.x) + p0.y*b0.y*__logf(p0.y)
         + p1.x*b0.z*__logf(p1.x) + p1.y*b0.w*__logf(p1.y)
         + p2.x*b1.x*__logf(p2.x) + p2.y*b1.y*__logf(p2.y)
         + p3.x*b1.z*__logf(p3.x) + p3.y*b1.w*__logf(p3.y);
}

// =================== THE megakernel ===================
__global__ void __launch_bounds__(TB, 1)
sinkhorn_mega(const float* __restrict__ x, const float* __restrict__ y, float* __restrict__ out) {
    int bk  = blockIdx.x;
    int tid = threadIdx.x;
    int batch = bk >> 3;
    int seg   = bk & 7;
    int w = tid >> 5, lane = tid & 31;

    // smem union: prologue xsh (bf16 x slice, 17408B) overlays loop's vec4/rsum/psum2 (12.8KB)
    __shared__ float4 smem_u[1088];                 // 17408 B
    __shared__ float  ys[64 * XS];                  // 17408 B (y chunk, tf32 values)
    __shared__ float  x2s[128], y2s[64];
    __shared__ int    s_done;
    __nv_bfloat16* xsh  = (__nv_bfloat16*)smem_u;   // stride XS (bf16 units)
    float4* vec4  = smem_u;                         // 256 float4 (b or a vector)
    float*  rsum  = (float*)((char*)smem_u + 4096); // 128 floats
    float2* psum2 = (float2*)((char*)smem_u + 4608);// 1024 float2
    float*  vecs  = (float*)vec4;
    float*  psum  = (float*)psum2;

    // ---- init own slices (covered by first grid barrier) ----
    if (tid < 128) {
        int gi = batch * NN + seg * 128 + tid;
        g_u[gi] = 0.f; g_v[gi] = 0.f; g_a[gi] = 1.f; g_b[gi] = 1.f;
    }

    // ---- softmax: own 128 x rows -> xsh(bf16)+x2s ; own 128 y rows -> g_ys(fp32)+g_y2 ----
    {
        int half = lane >> 4, hl = lane & 15;
        #pragma unroll
        for (int pass = 0; pass < 2; pass++) {
            int lr = pass * 64 + w * 2 + half;
            int grow = batch * NN + seg * 128 + lr;
            float4 e = ((const float4*)(x + (size_t)grow * DD))[hl];
            float m = fmaxf(fmaxf(e.x, e.y), fmaxf(e.z, e.w));
            #pragma unroll
            for (int o = 8; o; o >>= 1) m = fmaxf(m, __shfl_xor_sync(0xFFFFFFFFu, m, o));
            float s0 = __expf(e.x - m), s1 = __expf(e.y - m);
            float s2 = __expf(e.z - m), s3 = __expf(e.w - m);
            float s = (s0 + s1) + (s2 + s3);
            #pragma unroll
            for (int o = 8; o; o >>= 1) s += __shfl_xor_sync(0xFFFFFFFFu, s, o);
            float inv = 1.0f / s;
            float p0 = s0 * inv, p1 = s1 * inv, p2 = s2 * inv, p3 = s3 * inv;
            __nv_bfloat162 h0 = __floats2bfloat162_rn(p0, p1);
            __nv_bfloat162 h1 = __floats2bfloat162_rn(p2, p3);
            uint2 pk; pk.x = *(unsigned*)&h0; pk.y = *(unsigned*)&h1;
            *(uint2*)(xsh + lr * XS + hl * 4) = pk;
            float q = (p0 * p0 + p1 * p1) + (p2 * p2 + p3 * p3);
            #pragma unroll
            for (int o = 8; o; o >>= 1) q += __shfl_xor_sync(0xFFFFFFFFu, q, o);
            if (hl == 0) x2s[lr] = q;
        }
        #pragma unroll
        for (int pass = 0; pass < 2; pass++) {
            int lr = pass * 64 + w * 2 + half;
            int grow = batch * NN + seg * 128 + lr;
            float4 e = ((const float4*)(y + (size_t)grow * DD))[hl];
            float m = fmaxf(fmaxf(e.x, e.y), fmaxf(e.z, e.w));
            #pragma unroll
            for (int o = 8; o; o >>= 1) m = fmaxf(m, __shfl_xor_sync(0xFFFFFFFFu, m, o));
            float s0 = __expf(e.x - m), s1 = __expf(e.y - m);
            float s2 = __expf(e.z - m), s3 = __expf(e.w - m);
            float s = (s0 + s1) + (s2 + s3);
            #pragma unroll
            for (int o = 8; o; o >>= 1) s += __shfl_xor_sync(0xFFFFFFFFu, s, o);
            float inv = 1.0f / s;
            float p0 = s0 * inv, p1 = s1 * inv, p2 = s2 * inv, p3 = s3 * inv;
            ((float4*)(g_ys + (size_t)grow * DD))[hl] = make_float4(p0, p1, p2, p3);
            float q = (p0 * p0 + p1 * p1) + (p2 * p2 + p3 * p3);
            #pragma unroll
            for (int o = 8; o; o >>= 1) q += __shfl_xor_sync(0xFFFFFFFFu, q, o);
            if (hl == 0) g_y2[grow] = q;
        }
    }
    grid_barrier();   // all y softmax + inits visible

    // ---- buildK: own 128 rows x 1024 cols in 16 chunks of 64 cols ----
    {
        int mo = (w >> 2) * 16;        // 8 m-groups of 16 rows
        int wn = w & 3;                // 4 n-groups of 16 cols within chunk
        int gr = lane >> 2, gc = lane & 3;
        __nv_bfloat16* Kb = g_Kh + (size_t)(batch * NN + seg * 128) * NN;
        float xi0 = x2s[mo + gr], xi1 = x2s[mo + gr + 8];
        for (int c = 0; c < 16; c++) {
            __syncthreads();           // ys free
            {
                const float4* ysrc = (const float4*)(g_ys + (size_t)(batch * NN + c * 64) * DD);
                float4 vy = ysrc[tid];
                vy.x = to_tf32(vy.x); vy.y = to_tf32(vy.y);
                vy.z = to_tf32(vy.z); vy.w = to_tf32(vy.w);
                int row = tid >> 4, cc = (tid & 15) * 4;
                *((float4*)(ys + row * XS + cc)) = vy;
                if (tid < 64) y2s[tid] = g_y2[batch * NN + c * 64 + tid];
            }
            __syncthreads();
            float acc[2][4];
            #pragma unroll
            for (int nt = 0; nt < 2; nt++)
                #pragma unroll
                for (int q = 0; q < 4; q++) acc[nt][q] = 0.f;
            #pragma unroll
            for (int k0 = 0; k0 < 64; k0 += 8) {
                const __nv_bfloat16* ab = xsh + (mo + gr) * XS + k0 + gc;
                unsigned a0 = __float_as_uint(__bfloat162float(ab[0]));
                unsigned a1 = __float_as_uint(__bfloat162float(ab[8 * XS]));
                unsigned a2 = __float_as_uint(__bfloat162float(ab[4]));
                unsigned a3 = __float_as_uint(__bfloat162float(ab[8 * XS + 4]));
                #pragma unroll
                for (int nt = 0; nt < 2; nt++) {
                    const float* bb = ys + (wn * 16 + nt * 8 + gr) * XS + k0 + gc;
                    unsigned b0 = __float_as_uint(bb[0]);
                    unsigned b1 = __float_as_uint(bb[4]);
                    asm volatile(
                        "mma.sync.aligned.m16n8k8.row.col.f32.tf32.tf32.f32 "
                        "{%0,%1,%2,%3}, {%4,%5,%6,%7}, {%8,%9}, {%0,%1,%2,%3};"
                        : "+f"(acc[nt][0]), "+f"(acc[nt][1]), "+f"(acc[nt][2]), "+f"(acc[nt][3])
                        : "r"(a0), "r"(a1), "r"(a2), "r"(a3), "r"(b0), "r"(b1));
                }
            }
            #pragma unroll
            for (int nt = 0; nt < 2; nt++) {
                int nl = wn * 16 + nt * 8 + gc * 2;
                int jc = c * 64 + nl;
                float yj0 = y2s[nl], yj1 = y2s[nl + 1];
                float k00 = __expf((2.0f * acc[nt][0] - xi0 - yj0) * INV_EPS);
                float k01 = __expf((2.0f * acc[nt][1] - xi0 - yj1) * INV_EPS);
                float k10 = __expf((2.0f * acc[nt][2] - xi1 - yj0) * INV_EPS);
                float k11 = __expf((2.0f * acc[nt][3] - xi1 - yj1) * INV_EPS);
                *(__nv_bfloat162*)(Kb + (size_t)(mo + gr) * NN + jc)     = __floats2bfloat162_rn(k00, k01);
                *(__nv_bfloat162*)(Kb + (size_t)(mo + gr + 8) * NN + jc) = __floats2bfloat162_rn(k10, k11);
            }
        }
    }
    grid_barrier();   // full K of every batch ready (xsh dead from here)

    // ---- Sinkhorn loop: R5 phases verbatim; err via plain per-block slots ----
    int it = 0;
    for (; it < MAX_ITER; ++it) {
        // row phase: r_i = sum_j K_ij b_j ; update u, a
        if (tid < 256) vec4[tid] = ((const float4*)(g_b + batch * NN))[tid];
        __syncthreads();
        {
            int ibase = seg * 128 + w * 4;
            const uint4* K0 = (const uint4*)(g_Kh + (size_t)(batch * NN + ibase) * NN);
            float s0 = 0.f, s1 = 0.f, s2 = 0.f, s3 = 0.f;
            #pragma unroll
            for (int k = 0; k < 4; k++) {
                int idx = k * 32 + lane;
                float4 b0 = vec4[idx * 2], b1 = vec4[idx * 2 + 1];
                s0 += dot8(K0[          idx], b0, b1);
                s1 += dot8(K0[128 +     idx], b0, b1);
                s2 += dot8(K0[256 +     idx], b0, b1);
                s3 += dot8(K0[384 +     idx], b0, b1);
            }
            #pragma unroll
            for (int o = 16; o; o >>= 1) {
                s0 += __shfl_xor_sync(0xFFFFFFFFu, s0, o);
                s1 += __shfl_xor_sync(0xFFFFFFFFu, s1, o);
                s2 += __shfl_xor_sync(0xFFFFFFFFu, s2, o);
                s3 += __shfl_xor_sync(0xFFFFFFFFu, s3, o);
            }
            if (lane == 0) {
                rsum[w * 4 + 0] = s0; rsum[w * 4 + 1] = s1;
                rsum[w * 4 + 2] = s2; rsum[w * 4 + 3] = s3;
            }
        }
        __syncthreads();
        if (tid < 128) {
            int gi = batch * NN + seg * 128 + tid;
            float uo = g_u[gi];
            float a  = g_a[gi];
            float lse = logf(fmaf(a, rsum[tid], 1e-6f));
            float un  = EPSF * (LOG_MU - lse) + uo;
            g_u[gi] = un;
            g_a[gi] = expf(un * INV_EPS);
            psum[tid] = fabsf(un - uo);
        }
        __syncthreads();
        if (tid < 32) {
            float d = psum[tid] + psum[tid + 32] + psum[tid + 64] + psum[tid + 96];
            #pragma unroll
            for (int o = 16; o; o >>= 1) d += __shfl_xor_sync(0xFFFFFFFFu, d, o);
            if (tid == 0) g_errBlk[bk] = d;     // plain store; pre-barrier1
        }
        grid_barrier();   // new a + all err slots visible

        if (tid < 128) rsum[tid] = g_errBlk[tid];   // safe window: before barrier2

        // col phase: s_j = sum_i K_ij a_i ; update v, b
        if (tid < 256) vec4[tid] = ((const float4*)(g_a + batch * NN))[tid];
        __syncthreads();
        {
            int tx = tid & 63, ig = tid >> 6;
            const __nv_bfloat162* Kc =
                (const __nv_bfloat162*)(g_Kh + (size_t)(batch * NN + ig * 64) * NN)
                + seg * 64 + tx;
            const float* as = vecs + ig * 64;
            float sx = 0.f, sy = 0.f;
            #pragma unroll 8
            for (int i = 0; i < 64; i++) {
                float2 kv = __bfloat1622float2(Kc[(size_t)i * (NN / 2)]);
                float av = as[i];
                sx += kv.x * av; sy += kv.y * av;
            }
            psum2[tid] = make_float2(sx, sy);
        }
        __syncthreads();
        if (tid < 64) {
            float2 s = psum2[tid];
            #pragma unroll
            for (int k = 1; k < 16; k++) {
                float2 p = psum2[k * 64 + tid];
                s.x += p.x; s.y += p.y;
            }
            int gj = batch * NN + seg * 128 + tid * 2;
            float vo0 = g_v[gj], b0 = g_b[gj];
            float vo1 = g_v[gj + 1], b1 = g_b[gj + 1];
            float vn0 = EPSF * (LOG_MU - logf(fmaf(b0, s.x, 1e-6f))) + vo0;
            float vn1 = EPSF * (LOG_MU - logf(fmaf(b1, s.y, 1e-6f))) + vo1;
            g_v[gj]     = vn0;  g_b[gj]     = expf(vn0 * INV_EPS);
            g_v[gj + 1] = vn1;  g_b[gj + 1] = expf(vn1 * INV_EPS);
        }
        grid_barrier();   // new b visible everywhere

        // convergence verdict (identical on every block, from identical slots)
        if (tid < 32) {
            float e = rsum[tid] + rsum[tid + 32] + rsum[tid + 64] + rsum[tid + 96];
            #pragma unroll
            for (int o = 16; o; o >>= 1) e += __shfl_xor_sync(0xFFFFFFFFu, e, o);
            if (tid == 0) s_done = (e * (1.0f / BATCH) < THRESH) ? 1 : 0;
        }
        __syncthreads();
        if (s_done) break;
    }

    // ---- cost phase: -eps * sum_ij a_i b_j K_ij ln K_ij ----
    if (tid < 256) vec4[tid] = ((const float4*)(g_b + batch * NN))[tid];
    __syncthreads();
    {
        int ibase = seg * 128 + w * 4;
        const uint4* K0 = (const uint4*)(g_Kh + (size_t)(batch * NN + ibase) * NN);
        float s0 = 0.f, s1 = 0.f, s2 = 0.f, s3 = 0.f;
        #pragma unroll
        for (int k = 0; k < 4; k++) {
            int idx = k * 32 + lane;
            float4 b0 = vec4[idx * 2], b1 = vec4[idx * 2 + 1];
            s0 += dot8log(K0[          idx], b0, b1);
            s1 += dot8log(K0[128 +     idx], b0, b1);
            s2 += dot8log(K0[256 +     idx], b0, b1);
            s3 += dot8log(K0[384 +     idx], b0, b1);
        }
        #pragma unroll
        for (int o = 16; o; o >>= 1) {
            s0 += __shfl_xor_sync(0xFFFFFFFFu, s0, o);
            s1 += __shfl_xor_sync(0xFFFFFFFFu, s1, o);
            s2 += __shfl_xor_sync(0xFFFFFFFFu, s2, o);
            s3 += __shfl_xor_sync(0xFFFFFFFFu, s3, o);
        }
        if (lane == 0) {
            rsum[w * 4 + 0] = s0; rsum[w * 4 + 1] = s1;
            rsum[w * 4 + 2] = s2; rsum[w * 4 + 3] = s3;
        }
    }
    __syncthreads();
    if (tid < 128) {
        int gi = batch * NN + seg * 128 + tid;
        psum[tid] = g_a[gi] * rsum[tid];
    }
    __syncthreads();
    if (tid == 0) {
        float bsum = 0.f;
        #pragma unroll
        for (int k = 0; k < 128; k++) bsum += psum[k];
        g_costP[bk] = -EPSF * bsum;       // plain store
    }
    grid_barrier();
    if (bk == 0 && tid == 0) {
        double t = 0.0;
        for (int k = 0; k < GB; k++) t += (double)g_costP[k];
        out[0] = (float)(t * (1.0 / (double)BATCH));
    }
}

// ---------------- launch: ONE kernel ----------------
extern "C" void kernel_launch(void* const* d_in, const int* in_sizes, int n_in,
                              void* d_out, int out_size) {
    const float* x = (const float*)d_in[0];
    const float* y = (const float*)d_in[1];
    float* out = (float*)d_out;
    (void)in_sizes; (void)n_in; (void)out_size;

    sinkhorn_mega<<<GB, TB>>>(x, y, out);
}

// round 13
// speedup vs baseline: 1.2305x; 1.2305x over previous
#include <cuda_runtime.h>
#include <cuda_bf16.h>

#define BATCH 16
#define NN    1024
#define DD    64
#define EPSF      0.1f
#define INV_EPS   10.0f
#define LOG_MU   (-6.9314616f)   // log(1/1024 + 1e-8)
#define THRESH    0.1f
#define MAX_ITER  100
#define GB        128            // flat persistent grid: 128 blocks <= 148 SMs, co-resident
#define TB        1024

// ---------------- device scratch (static: no allocations allowed) ----------------
__device__ __nv_bfloat16 g_Kh[BATCH * NN * NN];  // 32 MB: K = exp(-C/eps), bf16
__device__ __nv_bfloat16 g_xsh[BATCH * NN * DD]; // 2 MB: softmaxed x, bf16 (exact tf32 subset)
__device__ __nv_bfloat16 g_ysh[BATCH * NN * DD]; // 2 MB: softmaxed y, bf16
__device__ float g_x2[BATCH * NN];
__device__ float g_y2[BATCH * NN];
__device__ float g_u [BATCH * NN];
__device__ float g_v [BATCH * NN];
__device__ float g_a [BATCH * NN];        // exp(u/eps)
__device__ float g_b [BATCH * NN];        // exp(v/eps)
__device__ float g_errA[MAX_ITER * BATCH];// per-iteration err slots (no reset races)
__device__ double   g_cost;
__device__ unsigned g_bar_cnt;
__device__ unsigned g_bar_gen;

// ---------------- software grid barrier (all GB blocks co-resident) ----------------
__device__ __forceinline__ void grid_barrier() {
    __threadfence();
    __syncthreads();
    if (threadIdx.x == 0) {
        unsigned gen = *((volatile unsigned*)&g_bar_gen);
        if (atomicAdd(&g_bar_cnt, 1u) == GB - 1u) {
            g_bar_cnt = 0u;
            __threadfence();
            *((volatile unsigned*)&g_bar_gen) = gen + 1u;
        } else {
            while (*((volatile unsigned*)&g_bar_gen) == gen) { __nanosleep(64); }
        }
    }
    __syncthreads();
}

// dot of 8 bf16 (one uint4) with 8 floats (two float4)
__device__ __forceinline__ float dot8(uint4 q, float4 b0, float4 b1) {
    float2 p0 = __bfloat1622float2(*(const __nv_bfloat162*)&q.x);
    float2 p1 = __bfloat1622float2(*(const __nv_bfloat162*)&q.y);
    float2 p2 = __bfloat1622float2(*(const __nv_bfloat162*)&q.z);
    float2 p3 = __bfloat1622float2(*(const __nv_bfloat162*)&q.w);
    return p0.x*b0.x + p0.y*b0.y + p1.x*b0.z + p1.y*b0.w
         + p2.x*b1.x + p2.y*b1.y + p3.x*b1.z + p3.y*b1.w;
}

// sum of k*b*ln(k) over 8 bf16 k's
__device__ __forceinline__ float dot8log(uint4 q, float4 b0, float4 b1) {
    float2 p0 = __bfloat1622float2(*(const __nv_bfloat162*)&q.x);
    float2 p1 = __bfloat1622float2(*(const __nv_bfloat162*)&q.y);
    float2 p2 = __bfloat1622float2(*(const __nv_bfloat162*)&q.z);
    float2 p3 = __bfloat1622float2(*(const __nv_bfloat162*)&q.w);
    return p0.x*b0.x*__logf(p0.x) + p0.y*b0.y*__logf(p0.y)
         + p1.x*b0.z*__logf(p1.x) + p1.y*b0.w*__logf(p1.y)
         + p2.x*b1.x*__logf(p2.x) + p2.y*b1.y*__logf(p2.y)
         + p3.x*b1.z*__logf(p3.x) + p3.y*b1.w*__logf(p3.y);
}

// ---------------- softmax (D=64): 2 rows/warp, float4 loads, bf16 stores + init ----------------
__global__ void softmax_kernel(const float* __restrict__ x, const float* __restrict__ y) {
    int gidx = blockIdx.x * blockDim.x + threadIdx.x;
    if (gidx < BATCH * NN) { g_u[gidx] = 0.f; g_v[gidx] = 0.f; g_a[gidx] = 1.f; g_b[gidx] = 1.f; }
    if (gidx < MAX_ITER * BATCH) g_errA[gidx] = 0.f;
    if (gidx == 0) { g_cost = 0.0; g_bar_cnt = 0u; g_bar_gen = 0u; }

    int gwarp = gidx >> 5;
    int lane  = threadIdx.x & 31;
    int half  = lane >> 4;             // two rows per warp, 16 lanes each
    int hl    = lane & 15;
    int row2  = gwarp * 2 + half;
    const float* src; __nv_bfloat16* dst; float* nrm; int row;
    if (row2 < BATCH * NN) { src = x; dst = g_xsh; nrm = g_x2; row = row2; }
    else                   { src = y; dst = g_ysh; nrm = g_y2; row = row2 - BATCH * NN; }

    float4 e = ((const float4*)(src + (size_t)row * DD))[hl];
    float m = fmaxf(fmaxf(e.x, e.y), fmaxf(e.z, e.w));
    #pragma unroll
    for (int o = 8; o; o >>= 1) m = fmaxf(m, __shfl_xor_sync(0xFFFFFFFFu, m, o));
    float s0 = __expf(e.x - m), s1 = __expf(e.y - m);
    float s2 = __expf(e.z - m), s3 = __expf(e.w - m);
    float s = (s0 + s1) + (s2 + s3);
    #pragma unroll
    for (int o = 8; o; o >>= 1) s += __shfl_xor_sync(0xFFFFFFFFu, s, o);
    float inv = 1.0f / s;
    float p0 = s0 * inv, p1 = s1 * inv, p2 = s2 * inv, p3 = s3 * inv;
    __nv_bfloat162 h0 = __floats2bfloat162_rn(p0, p1);
    __nv_bfloat162 h1 = __floats2bfloat162_rn(p2, p3);
    uint2 pk; pk.x = *(unsigned*)&h0; pk.y = *(unsigned*)&h1;
    *(uint2*)(dst + (size_t)row * DD + hl * 4) = pk;
    float q = (p0 * p0 + p1 * p1) + (p2 * p2 + p3 * p3);
    #pragma unroll
    for (int o = 8; o; o >>= 1) q += __shfl_xor_sync(0xFFFFFFFFu, q, o);
    if (hl == 0) nrm[row] = q;
}

// ---------------- K = exp((2 x.y - |x|^2 - |y|^2)/eps) via tf32 MMA, bf16 store ----------------
// Panels staged in bf16 (exact tf32 subset): halves buildK's L2 panel traffic.
#define XS_STRIDE 68   // (row*68+col)%32 = (row*4+col)%32 -> conflict-free fragment LDS
__global__ void __launch_bounds__(256) buildK_mma() {
    __shared__ float xs[64 * XS_STRIDE];
    __shared__ float ys[64 * XS_STRIDE];
    __shared__ float x2s[64], y2s[64];

    int bx = blockIdx.x;
    int batch = bx >> 8;          // 256 tiles per batch (16 i-tiles x 16 j-tiles)
    int tile  = bx & 255;
    int i0 = (tile >> 4) * 64, j0 = (tile & 15) * 64;
    int t = threadIdx.x;

    // load bf16 panels -> fp32 smem (values already exact tf32)
    const uint4* xsrc = (const uint4*)(g_xsh + (size_t)(batch * NN + i0) * DD);
    const uint4* ysrc = (const uint4*)(g_ysh + (size_t)(batch * NN + j0) * DD);
    #pragma unroll
    for (int k = 0; k < 2; k++) {
        int lin = k * 256 + t;               // 512 uint4 per panel (8 bf16 each)
        int row = lin >> 3, c = (lin & 7) * 8;
        uint4 qx = xsrc[lin];
        uint4 qy = ysrc[lin];
        float2 x0 = __bfloat1622float2(*(const __nv_bfloat162*)&qx.x);
        float2 x1 = __bfloat1622float2(*(const __nv_bfloat162*)&qx.y);
        float2 x2v = __bfloat1622float2(*(const __nv_bfloat162*)&qx.z);
        float2 x3 = __bfloat1622float2(*(const __nv_bfloat162*)&qx.w);
        float2 y0 = __bfloat1622float2(*(const __nv_bfloat162*)&qy.x);
        float2 y1 = __bfloat1622float2(*(const __nv_bfloat162*)&qy.y);
        float2 y2v = __bfloat1622float2(*(const __nv_bfloat162*)&qy.z);
        float2 y3 = __bfloat1622float2(*(const __nv_bfloat162*)&qy.w);
        float* xd = xs + row * XS_STRIDE + c;
        float* yd = ys + row * XS_STRIDE + c;
        *((float4*)(xd    )) = make_float4(x0.x, x0.y, x1.x, x1.y);
        *((float4*)(xd + 4)) = make_float4(x2v.x, x2v.y, x3.x, x3.y);
        *((float4*)(yd    )) = make_float4(y0.x, y0.y, y1.x, y1.y);
        *((float4*)(yd + 4)) = make_float4(y2v.x, y2v.y, y3.x, y3.y);
    }
    if (t < 64)            x2s[t]      = g_x2[batch * NN + i0 + t];
    else if (t < 128)      y2s[t - 64] = g_y2[batch * NN + j0 + (t - 64)];
    __syncthreads();

    int w = t >> 5, lane = t & 31;
    int mo = (w >> 1) * 16;
    int no = (w & 1) * 32;
    int gr = lane >> 2, gc = lane & 3;

    float acc[4][4];
    #pragma unroll
    for (int nt = 0; nt < 4; nt++)
        #pragma unroll
        for (int q = 0; q < 4; q++) acc[nt][q] = 0.f;

    #pragma unroll
    for (int k0 = 0; k0 < 64; k0 += 8) {
        unsigned a0, a1, a2, a3;
        {
            const float* base = xs + (mo + gr) * XS_STRIDE + k0 + gc;
            a0 = __float_as_uint(base[0]);
            a1 = __float_as_uint(base[8 * XS_STRIDE]);
            a2 = __float_as_uint(base[4]);
            a3 = __float_as_uint(base[8 * XS_STRIDE + 4]);
        }
        #pragma unroll
        for (int nt = 0; nt < 4; nt++) {
            const float* bb = ys + (no + nt * 8 + gr) * XS_STRIDE + k0 + gc;
            unsigned b0 = __float_as_uint(bb[0]);
            unsigned b1 = __float_as_uint(bb[4]);
            asm volatile(
                "mma.sync.aligned.m16n8k8.row.col.f32.tf32.tf32.f32 "
                "{%0,%1,%2,%3}, {%4,%5,%6,%7}, {%8,%9}, {%0,%1,%2,%3};"
                : "+f"(acc[nt][0]), "+f"(acc[nt][1]), "+f"(acc[nt][2]), "+f"(acc[nt][3])
                : "r"(a0), "r"(a1), "r"(a2), "r"(a3), "r"(b0), "r"(b1));
        }
    }

    __nv_bfloat16* Kb = g_Kh + (size_t)batch * NN * NN;
    float xi0 = x2s[mo + gr], xi1 = x2s[mo + gr + 8];
    int r0 = i0 + mo + gr, r1 = r0 + 8;
    #pragma unroll
    for (int nt = 0; nt < 4; nt++) {
        int jc = j0 + no + nt * 8 + gc * 2;
        float yj0 = y2s[no + nt * 8 + gc * 2];
        float yj1 = y2s[no + nt * 8 + gc * 2 + 1];
        float k00 = __expf((2.0f * acc[nt][0] - xi0 - yj0) * INV_EPS);
        float k01 = __expf((2.0f * acc[nt][1] - xi0 - yj1) * INV_EPS);
        float k10 = __expf((2.0f * acc[nt][2] - xi1 - yj0) * INV_EPS);
        float k11 = __expf((2.0f * acc[nt][3] - xi1 - yj1) * INV_EPS);
        *(__nv_bfloat162*)(Kb + (size_t)r0 * NN + jc) = __floats2bfloat162_rn(k00, k01);
        *(__nv_bfloat162*)(Kb + (size_t)r1 * NN + jc) = __floats2bfloat162_rn(k10, k11);
    }
}

// ---------------- persistent Sinkhorn loop + cost + finalize (R5 verbatim) ----------------
// Block bk: batch = bk>>3, seg = bk&7.
__global__ void __launch_bounds__(TB, 1) sinkhorn_persistent(float* __restrict__ out) {
    int bk  = blockIdx.x;
    int tid = threadIdx.x;
    int batch = bk >> 3;
    int seg   = bk & 7;
    int w = tid >> 5, lane = tid & 31;

    __shared__ float4 vec4[256];        // b (row/cost phases) or a (col phase), fp32
    __shared__ float  rsum[128];
    __shared__ float2 psum2[TB];
    __shared__ int    s_done;
    float* vecs = (float*)vec4;
    float* psum = (float*)psum2;

    int it = 0;
    for (; it < MAX_ITER; ++it) {
        // ======== row phase: r_i = sum_j K_ij b_j ; update u, a ========
        if (tid < 256) vec4[tid] = ((const float4*)(g_b + batch * NN))[tid];
        __syncthreads();
        {
            int ibase = seg * 128 + w * 4;      // 4 consecutive rows per warp
            const uint4* K0 = (const uint4*)(g_Kh + (size_t)(batch * NN + ibase) * NN);
            float s0 = 0.f, s1 = 0.f, s2 = 0.f, s3 = 0.f;
            #pragma unroll
            for (int k = 0; k < 4; k++) {
                int idx = k * 32 + lane;        // uint4 index within row (8 bf16 each)
                float4 b0 = vec4[idx * 2], b1 = vec4[idx * 2 + 1];
                s0 += dot8(K0[          idx], b0, b1);
                s1 += dot8(K0[128 +     idx], b0, b1);
                s2 += dot8(K0[256 +     idx], b0, b1);
                s3 += dot8(K0[384 +     idx], b0, b1);
            }
            #pragma unroll
            for (int o = 16; o; o >>= 1) {
                s0 += __shfl_xor_sync(0xFFFFFFFFu, s0, o);
                s1 += __shfl_xor_sync(0xFFFFFFFFu, s1, o);
                s2 += __shfl_xor_sync(0xFFFFFFFFu, s2, o);
                s3 += __shfl_xor_sync(0xFFFFFFFFu, s3, o);
            }
            if (lane == 0) {
                rsum[w * 4 + 0] = s0; rsum[w * 4 + 1] = s1;
                rsum[w * 4 + 2] = s2; rsum[w * 4 + 3] = s3;
            }
        }
        __syncthreads();
        if (tid < 128) {
            int gi = batch * NN + seg * 128 + tid;
            float uo = g_u[gi];
            float a  = g_a[gi];
            float lse = logf(fmaf(a, rsum[tid], 1e-6f));   // accurate log: iteration fidelity
            float un  = EPSF * (LOG_MU - lse) + uo;
            g_u[gi] = un;
            g_a[gi] = expf(un * INV_EPS);
            psum[tid] = fabsf(un - uo);
        }
        __syncthreads();
        if (tid < 32) {                 // warp-reduced derr
            float d = psum[tid] + psum[tid + 32] + psum[tid + 64] + psum[tid + 96];
            #pragma unroll
            for (int o = 16; o; o >>= 1) d += __shfl_xor_sync(0xFFFFFFFFu, d, o);
            if (tid == 0) atomicAdd(&g_errA[it * BATCH + batch], d);
        }
        grid_barrier();   // new a visible everywhere; err slot complete

        // ======== col phase: s_j = sum_i K_ij a_i ; update v, b ========
        if (tid < 256) vec4[tid] = ((const float4*)(g_a + batch * NN))[tid];
        __syncthreads();
        {
            int tx = tid & 63, ig = tid >> 6;   // 16 i-groups of 64 rows, 64 col-pairs
            const __nv_bfloat162* Kc =
                (const __nv_bfloat162*)(g_Kh + (size_t)(batch * NN + ig * 64) * NN)
                + seg * 64 + tx;
            const float* as = vecs + ig * 64;
            float sx = 0.f, sy = 0.f;
            #pragma unroll 8
            for (int i = 0; i < 64; i++) {
                float2 kv = __bfloat1622float2(Kc[(size_t)i * (NN / 2)]);
                float av = as[i];
                sx += kv.x * av; sy += kv.y * av;
            }
            psum2[tid] = make_float2(sx, sy);
        }
        __syncthreads();
        if (tid < 64) {
            float2 s = psum2[tid];
            #pragma unroll
            for (int k = 1; k < 16; k++) {
                float2 p = psum2[k * 64 + tid];
                s.x += p.x; s.y += p.y;
            }
            int gj = batch * NN + seg * 128 + tid * 2;
            float vo0 = g_v[gj], b0 = g_b[gj];
            float vo1 = g_v[gj + 1], b1 = g_b[gj + 1];
            float vn0 = EPSF * (LOG_MU - logf(fmaf(b0, s.x, 1e-6f))) + vo0;
            float vn1 = EPSF * (LOG_MU - logf(fmaf(b1, s.y, 1e-6f))) + vo1;
            g_v[gj]     = vn0;  g_b[gj]     = expf(vn0 * INV_EPS);
            g_v[gj + 1] = vn1;  g_b[gj + 1] = expf(vn1 * INV_EPS);
        }
        grid_barrier();   // new b visible; safe to read err and proceed

        // ======== convergence check (identical on every block) ========
        if (tid == 0) {
            float e = 0.f;
            #pragma unroll
            for (int bb = 0; bb < BATCH; bb++) e += g_errA[it * BATCH + bb];
            s_done = (e * (1.0f / BATCH) < THRESH) ? 1 : 0;
        }
        __syncthreads();
        if (s_done) break;
    }

    // ======== cost phase: -eps * sum_ij a_i b_j K_ij ln K_ij ========
    if (tid < 256) vec4[tid] = ((const float4*)(g_b + batch * NN))[tid];
    __syncthreads();
    {
        int ibase = seg * 128 + w * 4;
        const uint4* K0 = (const uint4*)(g_Kh + (size_t)(batch * NN + ibase) * NN);
        float s0 = 0.f, s1 = 0.f, s2 = 0.f, s3 = 0.f;
        #pragma unroll
        for (int k = 0; k < 4; k++) {
            int idx = k * 32 + lane;
            float4 b0 = vec4[idx * 2], b1 = vec4[idx * 2 + 1];
            s0 += dot8log(K0[          idx], b0, b1);
            s1 += dot8log(K0[128 +     idx], b0, b1);
            s2 += dot8log(K0[256 +     idx], b0, b1);
            s3 += dot8log(K0[384 +     idx], b0, b1);
        }
        #pragma unroll
        for (int o = 16; o; o >>= 1) {
            s0 += __shfl_xor_sync(0xFFFFFFFFu, s0, o);
            s1 += __shfl_xor_sync(0xFFFFFFFFu, s1, o);
            s2 += __shfl_xor_sync(0xFFFFFFFFu, s2, o);
            s3 += __shfl_xor_sync(0xFFFFFFFFu, s3, o);
        }
        if (lane == 0) {
            rsum[w * 4 + 0] = s0; rsum[w * 4 + 1] = s1;
            rsum[w * 4 + 2] = s2; rsum[w * 4 + 3] = s3;
        }
    }
    __syncthreads();
    if (tid < 128) {
        int gi = batch * NN + seg * 128 + tid;
        psum[tid] = g_a[gi] * rsum[tid];
    }
    __syncthreads();
    if (tid == 0) {
        float bsum = 0.f;
        #pragma unroll
        for (int k = 0; k < 128; k++) bsum += psum[k];
        atomicAdd(&g_cost, (double)(-EPSF * bsum));
    }
    grid_barrier();
    if (bk == 0 && tid == 0) out[0] = (float)(g_cost * (1.0 / (double)BATCH));
}

// ---------------- launch ----------------
extern "C" void kernel_launch(void* const* d_in, const int* in_sizes, int n_in,
                              void* d_out, int out_size) {
    const float* x = (const float*)d_in[0];
    const float* y = (const float*)d_in[1];
    float* out = (float*)d_out;
    (void)in_sizes; (void)n_in; (void)out_size;

    softmax_kernel<<<2048, 256>>>(x, y);   // 2 rows/warp softmax + init, bf16 stores
    buildK_mma<<<4096, 256>>>();           // bf16 panels -> tf32 HMMA -> bf16 K
    sinkhorn_persistent<<<GB, TB>>>(out);  // R5 persistent loop + cost + finalize
}